// round 17
// baseline (speedup 1.0000x reference)
#include <cuda_runtime.h>
#include <cuda_bf16.h>
#include <cuda_fp16.h>
#include <stdint.h>
#include <math.h>

#define BB 8
#define SS 2048
#define DM 1024
#define DK 512
#define DV 512
#define MTOK (BB*SS)   // 16384

// ---------------- scratch (static device allocations) ----------------
__device__ __align__(256) float  g_S   [(size_t)BB*SS*SS];    // 134 MB scores
__device__ __align__(256) __half g_sqh [(size_t)MTOK*DM];     // sq fp16 hi
__device__ __align__(256) __half g_sql [(size_t)MTOK*DM];     // sq fp16 lo
__device__ __align__(256) __half g_kvh [(size_t)MTOK*DM];     // kv fp16 hi (also single-fp16 kv)
__device__ __align__(256) __half g_kvl [(size_t)MTOK*DM];     // kv fp16 lo
__device__ __align__(256) __half g_wq16[(size_t)DK*DM];       // Wq^T single fp16
__device__ __align__(256) __half g_wk16[(size_t)DK*DM];       // Wk^T single fp16
__device__ __align__(256) __half g_wvh [(size_t)DV*DM];       // Wv^T fp16 hi
__device__ __align__(256) __half g_wvl [(size_t)DV*DM];       // Wv^T fp16 lo
__device__ __align__(256) __half g_q16 [(size_t)MTOK*DK];     // Q fp16
__device__ __align__(256) __half g_k16 [(size_t)MTOK*DK];     // K fp16
__device__ __align__(256) __half g_vt16[(size_t)DV*MTOK];     // V^T fp16 [512 x 16384]
__device__ __align__(256) __half g_p16 [(size_t)MTOK*SS];     // P fp16 (67 MB)

// ---------------- portable PTX helpers (sm_80+ only) ----------
__device__ __forceinline__ uint32_t s2u(const void* p) {
    return (uint32_t)__cvta_generic_to_shared(p);
}

#define CPA16(dst, src) \
    asm volatile("cp.async.cg.shared.global [%0], [%1], 16;" :: "r"(dst), "l"(src))

#define CPA_COMMIT() asm volatile("cp.async.commit_group;" ::: "memory")
#define CPA_WAIT0()  asm volatile("cp.async.wait_group 0;" ::: "memory")
#define CPA_WAIT1()  asm volatile("cp.async.wait_group 1;" ::: "memory")

#define LDSM_X4(r, addr) \
    asm volatile("ldmatrix.sync.aligned.m8n8.x4.shared.b16 {%0,%1,%2,%3}, [%4];" \
        : "=r"((r)[0]), "=r"((r)[1]), "=r"((r)[2]), "=r"((r)[3]) : "r"(addr))

#define MMA16816H(d, a, b) \
    asm volatile("mma.sync.aligned.m16n8k16.row.col.f32.f16.f16.f32 " \
        "{%0,%1,%2,%3}, {%4,%5,%6,%7}, {%8,%9}, {%0,%1,%2,%3};" \
        : "+f"((d)[0]), "+f"((d)[1]), "+f"((d)[2]), "+f"((d)[3]) \
        : "r"((a)[0]), "r"((a)[1]), "r"((a)[2]), "r"((a)[3]), \
          "r"((b)[0]), "r"((b)[1]))

// ---------------------------------------------------------------------------
// Shared fp16 GEMM core.
//   NSEG==2: acc += A0*B0^T + A1*B0^T   (A exact via hi/lo split, B quantized)
//   NSEG==1: acc += A0*B0^T
//   4 warps (2x2), warp tile 64x64, BK=64, 3-stage cp.async pipeline,
//   single-sync mainloop. Caller provides 96 KB dynamic smem.
//   Smem row = 64 elems = 128 B = 8 x 16B chunks; chunk c stored at c^(row&7).
//   KTRUNC: per-segment K truncated at bm0+128 (attn*V causal)
// ---------------------------------------------------------------------------
template <int NSEG, bool KTRUNC>
__device__ __forceinline__ void gemm_core(
    const __half* __restrict__ A0, const __half* __restrict__ A1,
    const __half* __restrict__ B0,
    int bm0, int bn0, int segK, int ldA, int ldB,
    float acc[4][8][4])
{
    extern __shared__ char sm[];
    const uint32_t smb = s2u(sm);
    const uint32_t aBuf[3] = { smb,         smb + 32768, smb + 65536 };
    const uint32_t bBuf[3] = { smb + 16384, smb + 49152, smb + 81920 };

    const int tid = threadIdx.x, wid = tid >> 5, lane = tid & 31;
    const int warp_m = (wid >> 1) * 64;   // 0 or 64
    const int warp_n = (wid & 1) * 64;    // 0 or 64

    int kEnd = segK;
    if (KTRUNC) { int l = bm0 + 128; kEnd = (l < segK) ? l : segK; }
    const int cps   = kEnd >> 6;          // 64-elem chunks per segment
    const int total = NSEG * cps;

    auto load_chunk = [&](int c, int buf) {
        int seg = (NSEG == 1) ? 0 : (c / cps);
        int ck  = (NSEG == 1) ? c : (c - seg * cps);
        const __half* Aseg = (seg == 1) ? A1 : A0;
        const __half* gA = Aseg + (size_t)bm0 * ldA + (ck << 6);
        const __half* gB = B0   + (size_t)bn0 * ldB + (ck << 6);
        const uint32_t bA = aBuf[buf], bB = bBuf[buf];
        #pragma unroll
        for (int t = 0; t < 8; ++t) {
            int f = tid + t * 128;            // 0..1023
            int row = f >> 3, cch = f & 7;
            int sw = cch ^ (row & 7);
            CPA16(bA + row * 128 + sw * 16, (const char*)(gA + (size_t)row * ldA) + cch * 16);
            CPA16(bB + row * 128 + sw * 16, (const char*)(gB + (size_t)row * ldB) + cch * 16);
        }
        CPA_COMMIT();
    };

    load_chunk(0, 0);
    load_chunk(1, 1);
    CPA_WAIT1();
    __syncthreads();

    const int wi = lane & 7, g = lane >> 3;   // ldmatrix lane-group decomposition

    int buf = 0;
    for (int c = 0; c < total; ++c) {
        const uint32_t bA = aBuf[buf], bB = bBuf[buf];
        int nb = buf + 2; if (nb >= 3) nb -= 3;

        #pragma unroll
        for (int ks = 0; ks < 4; ++ks) {
            if (ks == 1 && c + 2 < total) load_chunk(c + 2, nb);

            uint32_t a[4][4];
            #pragma unroll
            for (int mf = 0; mf < 4; ++mf) {
                int row = warp_m + mf * 16 + (g & 1) * 8 + wi;
                int cch = 2 * ks + (g >> 1);
                LDSM_X4(a[mf], bA + row * 128 + (cch ^ (row & 7)) * 16);
            }
            uint32_t b[8][2];
            #pragma unroll
            for (int p = 0; p < 4; ++p) {
                uint32_t r[4];
                int row = warp_n + p * 16 + (g >> 1) * 8 + wi;
                int cch = 2 * ks + (g & 1);
                LDSM_X4(r, bB + row * 128 + (cch ^ (row & 7)) * 16);
                b[2 * p + 0][0] = r[0]; b[2 * p + 0][1] = r[1];
                b[2 * p + 1][0] = r[2]; b[2 * p + 1][1] = r[3];
            }
            #pragma unroll
            for (int mf = 0; mf < 4; ++mf)
                #pragma unroll
                for (int nf = 0; nf < 8; ++nf)
                    MMA16816H(acc[mf][nf], a[mf], b[nf]);
        }

        if (c + 1 < total) {
            if (c + 2 < total) { CPA_WAIT1(); } else { CPA_WAIT0(); }
            __syncthreads();
        }
        if (++buf == 3) buf = 0;
    }
}

// epilogue: fp32 store. c-frag map: c0,c1 -> (lane/4, (lane%4)*2), c2,c3 -> row+8
__device__ __forceinline__ void epi_f32(
    float acc[4][8][4], float* __restrict__ Cf, int bm0, int bn0, int ldC)
{
    const int tid = threadIdx.x, wid = tid >> 5, lane = tid & 31;
    const int warp_m = (wid >> 1) * 64, warp_n = (wid & 1) * 64;
    const int rq = lane >> 2, cq = (lane & 3) * 2;
    #pragma unroll
    for (int mf = 0; mf < 4; ++mf)
        #pragma unroll
        for (int nf = 0; nf < 8; ++nf) {
            int m0 = bm0 + warp_m + mf * 16 + rq;
            int n0 = bn0 + warp_n + nf * 8 + cq;
            *(float2*)(Cf + (size_t)m0 * ldC + n0) =
                make_float2(acc[mf][nf][0], acc[mf][nf][1]);
            *(float2*)(Cf + (size_t)(m0 + 8) * ldC + n0) =
                make_float2(acc[mf][nf][2], acc[mf][nf][3]);
        }
}

// epilogue: single fp16 store
__device__ __forceinline__ void epi_f16(
    float acc[4][8][4], __half* __restrict__ C, int bm0, int bn0, int ldC)
{
    const int tid = threadIdx.x, wid = tid >> 5, lane = tid & 31;
    const int warp_m = (wid >> 1) * 64, warp_n = (wid & 1) * 64;
    const int rq = lane >> 2, cq = (lane & 3) * 2;
    #pragma unroll
    for (int mf = 0; mf < 4; ++mf)
        #pragma unroll
        for (int nf = 0; nf < 8; ++nf) {
            int m0 = bm0 + warp_m + mf * 16 + rq;
            int n0 = bn0 + warp_n + nf * 8 + cq;
            #pragma unroll
            for (int h = 0; h < 2; ++h) {
                __half2 v = __floats2half2_rn(acc[mf][nf][2 * h + 0],
                                              acc[mf][nf][2 * h + 1]);
                *(__half2*)(C + (size_t)(m0 + 8 * h) * ldC + n0) = v;
            }
        }
}

// ---------------------------------------------------------------------------
// All three projections in ONE launch (1536 CTAs), all 2-segment fp16:
//   Q : A = sq hi/lo,  B = Wq^T single     -> fp16 out
//   K : A = kv hi/lo,  B = Wk^T single     -> fp16 out
//   Vt: A = Wv^T hi/lo, B = kv hi (single) -> fp16 out (produced transposed)
// blockIdx.x: [0,512) -> Q, [512,1024) -> K, [1024,1536) -> Vt
// ---------------------------------------------------------------------------
__global__ void __launch_bounds__(128, 2) proj3_kernel(
    const __half* __restrict__ sqh, const __half* __restrict__ sql,
    const __half* __restrict__ kvh, const __half* __restrict__ kvl,
    const __half* __restrict__ wq16, const __half* __restrict__ wk16,
    const __half* __restrict__ wvh, const __half* __restrict__ wvl,
    __half* __restrict__ q16, __half* __restrict__ k16,
    __half* __restrict__ vt16)
{
    const int bx = blockIdx.x;
    const int p = bx >> 9;        // 0,1,2
    const int t = bx & 511;
    float acc[4][8][4] = {};
    if (p == 0) {
        int bm0 = (t >> 2) * 128, bn0 = (t & 3) * 128;
        gemm_core<2, false>(sqh, sql, wq16, bm0, bn0, DM, DM, DM, acc);
        epi_f16(acc, q16, bm0, bn0, DK);
    } else if (p == 1) {
        int bm0 = (t >> 2) * 128, bn0 = (t & 3) * 128;
        gemm_core<2, false>(kvh, kvl, wk16, bm0, bn0, DM, DM, DM, acc);
        epi_f16(acc, k16, bm0, bn0, DK);
    } else {
        int bm0 = (t & 3) * 128, bn0 = (t >> 2) * 128;
        gemm_core<2, false>(wvh, wvl, kvh, bm0, bn0, DM, DM, DM, acc);
        epi_f16(acc, vt16, bm0, bn0, MTOK);
    }
}

// ---------------------------------------------------------------------------
// Scores: S_b = Q_b * K_b^T, 1-term fp16, causal tile-skip, fp32 epilogue
// ---------------------------------------------------------------------------
__global__ void __launch_bounds__(128, 2) scores_kernel(
    const __half* __restrict__ q16, const __half* __restrict__ k16,
    float* __restrict__ Sb)
{
    const int bn0 = blockIdx.x * 128;
    const int bm0 = blockIdx.y * 128;
    if (bn0 >= bm0 + 128) return;    // above causal diagonal
    const long long z = blockIdx.z;
    const long long soff = z * (long long)SS * DK;
    float acc[4][8][4] = {};
    gemm_core<1, false>(q16 + soff, nullptr, k16 + soff,
                        bm0, bn0, DK, DK, DK, acc);
    epi_f32(acc, Sb + z * (long long)SS * SS, bm0, bn0, SS);
}

// ---------------------------------------------------------------------------
// attn*V: O_b = P_b * V_b, 1-term fp16, K truncated at causal diagonal.
// bm order REVERSED (longest-work CTAs first).
// ---------------------------------------------------------------------------
__global__ void __launch_bounds__(128, 2) attnv_kernel(
    const __half* __restrict__ p16, const __half* __restrict__ vt16,
    float* __restrict__ out)
{
    const int bn0 = blockIdx.x * 128;
    const int bm0 = (gridDim.y - 1 - blockIdx.y) * 128;   // longest first
    const long long z = blockIdx.z;
    float acc[4][8][4] = {};
    gemm_core<1, true>(p16 + z * (long long)SS * SS, nullptr,
                       vt16 + z * (long long)SS,
                       bm0, bn0, SS, SS, MTOK, acc);
    epi_f32(acc, out + z * (long long)SS * DV, bm0, bn0, DV);
}

// ---------------------------------------------------------------------------
// fp32 -> fp16 (hi, lo) split for both sources in one launch (grid.y selects)
// ---------------------------------------------------------------------------
__global__ void __launch_bounds__(256) split2_kernel(
    const float* __restrict__ x0, __half* __restrict__ h0, __half* __restrict__ l0,
    const float* __restrict__ x1, __half* __restrict__ h1, __half* __restrict__ l1)
{
    const float* x = blockIdx.y ? x1 : x0;
    __half* h = blockIdx.y ? h1 : h0;
    __half* l = blockIdx.y ? l1 : l0;
    int i = (blockIdx.x * 256 + threadIdx.x) * 8;
    float4 a = *(const float4*)(x + i);
    float4 b = *(const float4*)(x + i + 4);
    float v[8] = {a.x, a.y, a.z, a.w, b.x, b.y, b.z, b.w};
    union { __half hh[8]; uint4 u; } H, L;
    #pragma unroll
    for (int j = 0; j < 8; ++j) {
        __half hv = __float2half_rn(v[j]);
        H.hh[j] = hv;
        L.hh[j] = __float2half_rn(v[j] - __half2float(hv));
    }
    *(uint4*)(h + i) = H.u;
    *(uint4*)(l + i) = L.u;
}

// Weights fp32 [DM x 512] -> transposed fp16 [512 x DM].
// grid.y: 0 -> Wq single, 1 -> Wk single, 2 -> Wv hi/lo
__global__ void __launch_bounds__(256) splitw3_kernel(
    const float* __restrict__ W0, __half* __restrict__ o0,
    const float* __restrict__ W1, __half* __restrict__ o1,
    const float* __restrict__ W2, __half* __restrict__ h2, __half* __restrict__ l2)
{
    int o = blockIdx.x * 256 + threadIdx.x;   // o = n*DM + k, n<512
    int n = o >> 10, k = o & 1023;
    if (blockIdx.y == 0) {
        o0[o] = __float2half_rn(W0[(size_t)k * 512 + n]);
    } else if (blockIdx.y == 1) {
        o1[o] = __float2half_rn(W1[(size_t)k * 512 + n]);
    } else {
        float v = W2[(size_t)k * 512 + n];
        __half hv = __float2half_rn(v);
        h2[o] = hv;
        l2[o] = __float2half_rn(v - __half2float(hv));
    }
}

// ---------------------------------------------------------------------------
// fused mask + softmax reading fp32 scores, writing fp16 probabilities
// ---------------------------------------------------------------------------
__global__ void __launch_bounds__(256) softmax_f16(
    const float* __restrict__ S, __half* __restrict__ P,
    const int* __restrict__ qpad, const int* __restrict__ kpad, float scale)
{
    const int r = blockIdx.x;
    const int b = r >> 11, i = r & (SS - 1);
    const float* row = S + (size_t)r * SS;
    const int* kp = kpad + b * SS;
    const bool qp = (qpad[r] != 0);
    const int tid = threadIdx.x, j0 = tid * 8;
    const int lane = tid & 31, warp = tid >> 5;

    float4 a = ((const float4*)(row + j0))[0];
    float4 c = ((const float4*)(row + j0))[1];
    int4 ka = ((const int4*)(kp + j0))[0];
    int4 kb = ((const int4*)(kp + j0))[1];
    float x[8] = {a.x, a.y, a.z, a.w, c.x, c.y, c.z, c.w};
    int km[8] = {ka.x, ka.y, ka.z, ka.w, kb.x, kb.y, kb.z, kb.w};

    float m = -INFINITY;
    #pragma unroll
    for (int u = 0; u < 8; ++u) {
        bool valid = (!qp) && (j0 + u <= i) && (km[u] == 0);
        x[u] = valid ? x[u] * scale : -INFINITY;
        m = fmaxf(m, x[u]);
    }

    __shared__ float redm[8], reds[8];
    #pragma unroll
    for (int o = 16; o; o >>= 1) m = fmaxf(m, __shfl_xor_sync(0xffffffffu, m, o));
    if (lane == 0) redm[warp] = m;
    __syncthreads();
    float bm = -INFINITY;
    #pragma unroll
    for (int w = 0; w < 8; ++w) bm = fmaxf(bm, redm[w]);

    uint4* op = (uint4*)(P + (size_t)r * SS + j0);

    if (bm == -INFINITY) {     // fully masked row -> zeros
        *op = make_uint4(0, 0, 0, 0);
        return;
    }

    float e[8];
    float s = 0.0f;
    #pragma unroll
    for (int u = 0; u < 8; ++u) {
        e[u] = (x[u] == -INFINITY) ? 0.0f : __expf(x[u] - bm);
        s += e[u];
    }
    #pragma unroll
    for (int o = 16; o; o >>= 1) s += __shfl_xor_sync(0xffffffffu, s, o);
    if (lane == 0) reds[warp] = s;
    __syncthreads();
    float bs = 0.0f;
    #pragma unroll
    for (int w = 0; w < 8; ++w) bs += reds[w];

    const float rinv = 1.0f / bs;
    union { __half2 hh[4]; uint4 u; } O;
    #pragma unroll
    for (int u = 0; u < 4; ++u)
        O.hh[u] = __floats2half2_rn(e[2 * u] * rinv, e[2 * u + 1] * rinv);
    *op = O.u;
}

// ---------------------------------------------------------------------------
extern "C" void kernel_launch(void* const* d_in, const int* in_sizes, int n_in,
                              void* d_out, int out_size)
{
    const float* sq   = (const float*)d_in[0];
    const float* skv  = (const float*)d_in[1];
    const int*   qpad = (const int*)d_in[2];
    const int*   kpad = (const int*)d_in[3];
    const float* Wq   = (const float*)d_in[4];
    const float* Wk   = (const float*)d_in[5];
    const float* Wv   = (const float*)d_in[6];
    float* out = (float*)d_out;

    float *Sb;
    __half *sqh, *sql, *kvh, *kvl, *wq16, *wk16, *wvh, *wvl;
    __half *q16, *k16, *vt16, *p16;
    cudaGetSymbolAddress((void**)&Sb,   g_S);
    cudaGetSymbolAddress((void**)&sqh,  g_sqh);  cudaGetSymbolAddress((void**)&sql, g_sql);
    cudaGetSymbolAddress((void**)&kvh,  g_kvh);  cudaGetSymbolAddress((void**)&kvl, g_kvl);
    cudaGetSymbolAddress((void**)&wq16, g_wq16); cudaGetSymbolAddress((void**)&wk16, g_wk16);
    cudaGetSymbolAddress((void**)&wvh,  g_wvh);  cudaGetSymbolAddress((void**)&wvl, g_wvl);
    cudaGetSymbolAddress((void**)&q16,  g_q16);  cudaGetSymbolAddress((void**)&k16, g_k16);
    cudaGetSymbolAddress((void**)&vt16, g_vt16);
    cudaGetSymbolAddress((void**)&p16,  g_p16);

    const int SMEMSZ = 98304;   // 3 x (16 KB A + 16 KB B)
    cudaFuncSetAttribute(proj3_kernel,
                         cudaFuncAttributeMaxDynamicSharedMemorySize, SMEMSZ);
    cudaFuncSetAttribute(scores_kernel,
                         cudaFuncAttributeMaxDynamicSharedMemorySize, SMEMSZ);
    cudaFuncSetAttribute(attnv_kernel,
                         cudaFuncAttributeMaxDynamicSharedMemorySize, SMEMSZ);

    // 1) split both sources to fp16 hi/lo (one launch)
    const int nsrc = MTOK * DM;                    // 16.7M
    split2_kernel<<<dim3(nsrc / 2048, 2), 256>>>(sq, sqh, sql, skv, kvh, kvl);
    // 2) transpose weights: Wq,Wk single fp16; Wv fp16 hi/lo (one launch)
    splitw3_kernel<<<dim3((DK * DM) / 256, 3), 256>>>(
        Wq, wq16, Wk, wk16, Wv, wvh, wvl);

    // 3) all three projections in ONE launch (1536 CTAs), 2-segment fp16
    proj3_kernel<<<1536, 128, SMEMSZ>>>(
        sqh, sql, kvh, kvl, wq16, wk16, wvh, wvl, q16, k16, vt16);

    // 4) scores S_b = Q_b * K_b^T (1-term fp16, causal tile-skip), fp32 epilogue
    scores_kernel<<<dim3(SS / 128, SS / 128, BB), 128, SMEMSZ>>>(q16, k16, Sb);

    // 5) mask + softmax -> P fp16
    const float scale = 0.04419417382415922f;   // 1/sqrt(512)
    softmax_f16<<<MTOK, 256>>>(Sb, p16, qpad, kpad, scale);

    // 6) O_b = P_b * V_b (1-term fp16, K truncated at causal diagonal,
    //    longest-first order)
    attnv_kernel<<<dim3(DV / 128, SS / 128, BB), 128, SMEMSZ>>>(
        p16, vt16, out);
}